// round 1
// baseline (speedup 1.0000x reference)
#include <cuda_runtime.h>
#include <cuda_bf16.h>
#include <cstdint>

// ---------------------------------------------------------------------------
// Voxelizer: volume[z,y,x] = sum_n density[n] * exp(-0.5 * d^T C_n^{-1} d),
//   d = (vz,vy,vx) - positions[n]   (reference grid order is (z,y,x), x fast)
//   C^{-1} = R diag(1/(s^2+1e-8)) R^T
//
// Strategy:
//  - precompute kernel: per gaussian, 6 symmetric coeffs of k*C^{-1}
//    (k = -0.5*log2(e), so exp(-0.5 m) == exp2(sum)), position, density,
//    and a conservative cull radius^2 = 40 * max(s^2).
//  - main kernel: 256-thread blocks own a 16x8x8 voxel tile; each thread
//    owns 4 consecutive x voxels. Per gaussian, hoist the quadratic-in-dx
//    decomposition (A,B,C) so each voxel is 2 FMA + 1 EX2 + 1 FMA.
//  - per-tile conservative culling (box distance vs 40*smax^2), compacted
//    deterministically with ballot+scan.
// ---------------------------------------------------------------------------

#define MAX_N 4096
__device__ float4 g_gauss[3 * MAX_N];

__device__ __forceinline__ float ex2_approx(float x) {
    float y;
    asm("ex2.approx.ftz.f32 %0, %1;" : "=f"(y) : "f"(x));
    return y;
}

__global__ void precompute_kernel(const float* __restrict__ pos,
                                  const float* __restrict__ scl,
                                  const float* __restrict__ rot,
                                  const float* __restrict__ den,
                                  int N) {
    int i = blockIdx.x * blockDim.x + threadIdx.x;
    if (i >= N) return;

    float qw = rot[4 * i + 0], qx = rot[4 * i + 1];
    float qy = rot[4 * i + 2], qz = rot[4 * i + 3];
    float qn = rsqrtf(qw * qw + qx * qx + qy * qy + qz * qz);
    qw *= qn; qx *= qn; qy *= qn; qz *= qn;

    float r00 = 1.f - 2.f * (qy * qy + qz * qz);
    float r01 = 2.f * (qx * qy - qw * qz);
    float r02 = 2.f * (qx * qz + qw * qy);
    float r10 = 2.f * (qx * qy + qw * qz);
    float r11 = 1.f - 2.f * (qx * qx + qz * qz);
    float r12 = 2.f * (qy * qz - qw * qx);
    float r20 = 2.f * (qx * qz - qw * qy);
    float r21 = 2.f * (qy * qz + qw * qx);
    float r22 = 1.f - 2.f * (qx * qx + qy * qy);

    float s0 = scl[3 * i + 0], s1 = scl[3 * i + 1], s2 = scl[3 * i + 2];
    float i0 = 1.f / (s0 * s0 + 1e-8f);
    float i1 = 1.f / (s1 * s1 + 1e-8f);
    float i2 = 1.f / (s2 * s2 + 1e-8f);

    // cov_inv[a][b] = sum_k R[a][k] * inv_s2[k] * R[b][k]
    float c00 = r00 * r00 * i0 + r01 * r01 * i1 + r02 * r02 * i2;
    float c11 = r10 * r10 * i0 + r11 * r11 * i1 + r12 * r12 * i2;
    float c22 = r20 * r20 * i0 + r21 * r21 * i1 + r22 * r22 * i2;
    float c01 = r00 * r10 * i0 + r01 * r11 * i1 + r02 * r12 * i2;
    float c02 = r00 * r20 * i0 + r01 * r21 * i1 + r02 * r22 * i2;
    float c12 = r10 * r20 * i0 + r11 * r21 * i1 + r12 * r22 * i2;

    const float k = -0.5f * 1.4426950408889634f;  // exp(-0.5m) = 2^(k*m)

    float smax2 = fmaxf(s0 * s0, fmaxf(s1 * s1, s2 * s2)) + 1e-8f;
    float rcut2 = 40.f * smax2;  // skipped term <= exp(-20) ~ 2e-9

    float p0 = pos[3 * i + 0];  // z-axis component
    float p1 = pos[3 * i + 1];  // y
    float p2 = pos[3 * i + 2];  // x (fast axis)

    // Inner-loop variable u = dx (component 2). Layout:
    //  A = (k*c22 [u^2], k*c11 [dy^2], k*c00 [dz^2], 2k*c12 [u*dy])
    //  B = (2k*c02 [u*dz], 2k*c01 [dy*dz], px, py)
    //  C = (pz, density, rcut2, 0)
    g_gauss[3 * i + 0] = make_float4(k * c22, k * c11, k * c00, 2.f * k * c12);
    g_gauss[3 * i + 1] = make_float4(2.f * k * c02, 2.f * k * c01, p2, p1);
    g_gauss[3 * i + 2] = make_float4(p0, den[i], rcut2, 0.f);
}

// Tile: 16 (x) x 8 (y) x 8 (z) voxels; 256 threads, each owns 4 x-voxels.
#define DIMX 128
#define DIMY 128
#define DIMZ 128
#define TILE_X 16
#define TILE_Y 8
#define TILE_Z 8

__global__ __launch_bounds__(256)
void voxelize_kernel(float* __restrict__ out, int N) {
    __shared__ float4 sg[3 * 256];
    __shared__ int slist[256];
    __shared__ int swcnt[8];

    const float h = 2.0f / (float)(DIMX - 1);
    const int tid  = threadIdx.x;
    const int lane = tid & 31;
    const int wid  = tid >> 5;

    const int xq = tid & 3;            // x-quad within tile
    const int ty = (tid >> 2) & 7;     // y within tile
    const int tz = tid >> 5;           // z within tile

    const int gx = blockIdx.x * TILE_X + xq * 4;
    const int gy = blockIdx.y * TILE_Y + ty;
    const int gz = blockIdx.z * TILE_Z + tz;

    const float x0 = -1.f + h * (float)gx;
    const float vy = -1.f + h * (float)gy;
    const float vz = -1.f + h * (float)gz;

    // Tile bounding box (for culling)
    const float cx = -1.f + h * ((float)(blockIdx.x * TILE_X) + (TILE_X - 1) * 0.5f);
    const float cy = -1.f + h * ((float)(blockIdx.y * TILE_Y) + (TILE_Y - 1) * 0.5f);
    const float cz = -1.f + h * ((float)(blockIdx.z * TILE_Z) + (TILE_Z - 1) * 0.5f);
    const float hx = (TILE_X - 1) * 0.5f * h;
    const float hy = (TILE_Y - 1) * 0.5f * h;
    const float hz = (TILE_Z - 1) * 0.5f * h;

    float acc0 = 0.f, acc1 = 0.f, acc2 = 0.f, acc3 = 0.f;

    for (int base = 0; base < N; base += 256) {
        const int nch = min(256, N - base);

        // Stage this chunk's params into smem (coalesced float4 copy)
        for (int j = tid; j < 3 * nch; j += 256)
            sg[j] = g_gauss[3 * base + j];
        __syncthreads();

        // Cull: box distance^2 from tile to gaussian center vs rcut2
        bool keep = false;
        if (tid < nch) {
            float px = sg[3 * tid + 1].z;   // x
            float py = sg[3 * tid + 1].w;   // y
            float pz = sg[3 * tid + 2].x;   // z
            float dx = fmaxf(fabsf(px - cx) - hx, 0.f);
            float dy = fmaxf(fabsf(py - cy) - hy, 0.f);
            float dz = fmaxf(fabsf(pz - cz) - hz, 0.f);
            float d2 = dx * dx + dy * dy + dz * dz;
            keep = (d2 <= sg[3 * tid + 2].z);
        }
        // Deterministic compaction (ballot + per-warp scan)
        unsigned m = __ballot_sync(0xffffffffu, keep);
        if (lane == 0) swcnt[wid] = __popc(m);
        __syncthreads();
        int wbase = 0;
#pragma unroll
        for (int w = 0; w < 8; w++)
            if (w < wid) wbase += swcnt[w];
        if (keep)
            slist[wbase + __popc(m & ((1u << lane) - 1u))] = tid;
        __syncthreads();
        int cnt = swcnt[0] + swcnt[1] + swcnt[2] + swcnt[3] +
                  swcnt[4] + swcnt[5] + swcnt[6] + swcnt[7];

        for (int g = 0; g < cnt; g++) {
            const int idx = slist[g];
            const float4 A  = sg[3 * idx + 0];
            const float4 Bv = sg[3 * idx + 1];
            const float4 Cv = sg[3 * idx + 2];

            const float dy = vy - Bv.w;
            const float dz = vz - Cv.x;
            const float u0 = x0 - Bv.z;
            const float w  = Cv.y;

            // mahal*k = A.x*u^2 + bb*u + cc
            const float bb = fmaf(A.w, dy, Bv.x * dz);
            const float cc = fmaf(dy, fmaf(A.y, dy, Bv.y * dz), (A.z * dz) * dz);

            float u, mm, e;
            u = u0;
            mm = fmaf(fmaf(A.x, u, bb), u, cc);
            e = ex2_approx(mm); acc0 = fmaf(e, w, acc0);
            u = u0 + h;
            mm = fmaf(fmaf(A.x, u, bb), u, cc);
            e = ex2_approx(mm); acc1 = fmaf(e, w, acc1);
            u = u0 + 2.f * h;
            mm = fmaf(fmaf(A.x, u, bb), u, cc);
            e = ex2_approx(mm); acc2 = fmaf(e, w, acc2);
            u = u0 + 3.f * h;
            mm = fmaf(fmaf(A.x, u, bb), u, cc);
            e = ex2_approx(mm); acc3 = fmaf(e, w, acc3);
        }
        __syncthreads();  // protect smem before next chunk reload
    }

    // Store 4 consecutive x voxels as one float4 (gx % 4 == 0)
    const size_t vidx = ((size_t)gz * DIMY + gy) * DIMX + gx;
    float4 r = make_float4(acc0, acc1, acc2, acc3);
    *reinterpret_cast<float4*>(out + vidx) = r;
}

extern "C" void kernel_launch(void* const* d_in, const int* in_sizes, int n_in,
                              void* d_out, int out_size) {
    const float* positions = (const float*)d_in[0];
    const float* scales    = (const float*)d_in[1];
    const float* rotations = (const float*)d_in[2];
    const float* density   = (const float*)d_in[3];
    const int N = in_sizes[3];  // density element count

    precompute_kernel<<<(N + 255) / 256, 256>>>(positions, scales, rotations, density, N);

    dim3 grid(DIMX / TILE_X, DIMY / TILE_Y, DIMZ / TILE_Z);  // (8,16,16)
    voxelize_kernel<<<grid, 256>>>((float*)d_out, N);
}

// round 4
// speedup vs baseline: 1.3220x; 1.3220x over previous
#include <cuda_runtime.h>
#include <cuda_bf16.h>
#include <cstdint>

// ---------------------------------------------------------------------------
// Voxelizer: volume[z,y,x] = sum_n density[n] * exp(-0.5 * d^T C_n^{-1} d)
//
// R2: sliding-Gaussian recurrence along x. For the row of voxels a thread
// owns, exp2(m(u+h)) = exp2(m(u)) * G(u), G(u+h) = G(u)*r with r constant
// per gaussian. 2 MUFU per (gaussian,thread) instead of 8; each voxel is
// 1 FMA + 2 FMUL on the (underutilized) FMA pipe.
// ---------------------------------------------------------------------------

#define MAX_N 4096
__device__ float4 g_gauss[4 * MAX_N];

#define DIMX 128
#define DIMY 128
#define DIMZ 128
#define RUNX 8      // x-voxels per thread (safety bound: see analysis)
#define TILE_Y 16
#define TILE_Z 16
#define HSTEP (2.0f / 127.0f)

__device__ __forceinline__ float ex2_approx(float x) {
    float y;
    asm("ex2.approx.ftz.f32 %0, %1;" : "=f"(y) : "f"(x));
    return y;
}

__global__ void precompute_kernel(const float* __restrict__ pos,
                                  const float* __restrict__ scl,
                                  const float* __restrict__ rot,
                                  const float* __restrict__ den,
                                  int N) {
    int i = blockIdx.x * blockDim.x + threadIdx.x;
    if (i >= N) return;

    float qw = rot[4 * i + 0], qx = rot[4 * i + 1];
    float qy = rot[4 * i + 2], qz = rot[4 * i + 3];
    float qn = rsqrtf(qw * qw + qx * qx + qy * qy + qz * qz);
    qw *= qn; qx *= qn; qy *= qn; qz *= qn;

    float r00 = 1.f - 2.f * (qy * qy + qz * qz);
    float r01 = 2.f * (qx * qy - qw * qz);
    float r02 = 2.f * (qx * qz + qw * qy);
    float r10 = 2.f * (qx * qy + qw * qz);
    float r11 = 1.f - 2.f * (qx * qx + qz * qz);
    float r12 = 2.f * (qy * qz - qw * qx);
    float r20 = 2.f * (qx * qz - qw * qy);
    float r21 = 2.f * (qy * qz + qw * qx);
    float r22 = 1.f - 2.f * (qx * qx + qy * qy);

    float s0 = scl[3 * i + 0], s1 = scl[3 * i + 1], s2 = scl[3 * i + 2];
    float i0 = 1.f / (s0 * s0 + 1e-8f);
    float i1 = 1.f / (s1 * s1 + 1e-8f);
    float i2 = 1.f / (s2 * s2 + 1e-8f);

    float c00 = r00 * r00 * i0 + r01 * r01 * i1 + r02 * r02 * i2;
    float c11 = r10 * r10 * i0 + r11 * r11 * i1 + r12 * r12 * i2;
    float c22 = r20 * r20 * i0 + r21 * r21 * i1 + r22 * r22 * i2;
    float c01 = r00 * r10 * i0 + r01 * r11 * i1 + r02 * r12 * i2;
    float c02 = r00 * r20 * i0 + r01 * r21 * i1 + r02 * r22 * i2;
    float c12 = r10 * r20 * i0 + r11 * r21 * i1 + r12 * r22 * i2;

    const float k = -0.5f * 1.4426950408889634f;  // exp(-0.5m) = 2^(k*m)

    float smax2 = fmaxf(s0 * s0, fmaxf(s1 * s1, s2 * s2)) + 1e-8f;
    float rcut2 = 40.f * smax2;  // skipped term <= exp(-20) ~ 2e-9

    float p0 = pos[3 * i + 0];  // z
    float p1 = pos[3 * i + 1];  // y
    float p2 = pos[3 * i + 2];  // x (fast axis)

    float a   = k * c22;                 // coef of dx^2 (log2 domain, < 0)
    float h   = HSTEP;
    float a2h = 2.f * a * h;
    float ah2 = a * h * h;
    float rr  = exp2f(2.f * a * h * h);  // per-step ratio of G, in (0.5, 1]

    // Layout (4 x float4 per gaussian):
    //  f0 = (a, k*c11 [dy^2], k*c00 [dz^2], 2k*c12 [u*dy])
    //  f1 = (2k*c02 [u*dz], 2k*c01 [dy*dz], px, py)
    //  f2 = (pz, density, rcut2, r)
    //  f3 = (2ah, ah^2, 0, 0)
    g_gauss[4 * i + 0] = make_float4(a, k * c11, k * c00, 2.f * k * c12);
    g_gauss[4 * i + 1] = make_float4(2.f * k * c02, 2.f * k * c01, p2, p1);
    g_gauss[4 * i + 2] = make_float4(p0, den[i], rcut2, rr);
    g_gauss[4 * i + 3] = make_float4(a2h, ah2, 0.f, 0.f);
}

__global__ __launch_bounds__(256)
void voxelize_kernel(float* __restrict__ out, int N) {
    __shared__ float4 sg[4 * 256];
    __shared__ int slist[256];
    __shared__ int swcnt[8];

    const float h = HSTEP;
    const int tid  = threadIdx.x;
    const int lane = tid & 31;
    const int wid  = tid >> 5;

    const int ty = tid & 15;
    const int tz = tid >> 4;

    const int gx = blockIdx.x * RUNX;          // whole block shares x-range
    const int gy = blockIdx.y * TILE_Y + ty;
    const int gz = blockIdx.z * TILE_Z + tz;

    const float x0 = -1.f + h * (float)gx;
    const float vy = -1.f + h * (float)gy;
    const float vz = -1.f + h * (float)gz;

    // Tile bounding box for culling
    const float cx = -1.f + h * ((float)(blockIdx.x * RUNX)   + (RUNX   - 1) * 0.5f);
    const float cy = -1.f + h * ((float)(blockIdx.y * TILE_Y) + (TILE_Y - 1) * 0.5f);
    const float cz = -1.f + h * ((float)(blockIdx.z * TILE_Z) + (TILE_Z - 1) * 0.5f);
    const float hx = (RUNX   - 1) * 0.5f * h;
    const float hy = (TILE_Y - 1) * 0.5f * h;
    const float hz = (TILE_Z - 1) * 0.5f * h;

    float acc[RUNX];
#pragma unroll
    for (int v = 0; v < RUNX; v++) acc[v] = 0.f;

    for (int base = 0; base < N; base += 256) {
        const int nch = min(256, N - base);

        for (int j = tid; j < 4 * nch; j += 256)
            sg[j] = g_gauss[4 * base + j];
        __syncthreads();

        // Conservative cull: box distance^2 vs rcut2
        bool keep = false;
        if (tid < nch) {
            float px = sg[4 * tid + 1].z;
            float py = sg[4 * tid + 1].w;
            float pz = sg[4 * tid + 2].x;
            float dx = fmaxf(fabsf(px - cx) - hx, 0.f);
            float dy = fmaxf(fabsf(py - cy) - hy, 0.f);
            float dz = fmaxf(fabsf(pz - cz) - hz, 0.f);
            float d2 = dx * dx + dy * dy + dz * dz;
            keep = (d2 <= sg[4 * tid + 2].z);
        }
        unsigned m = __ballot_sync(0xffffffffu, keep);
        if (lane == 0) swcnt[wid] = __popc(m);
        __syncthreads();
        int wbase = 0;
#pragma unroll
        for (int w = 0; w < 8; w++)
            if (w < wid) wbase += swcnt[w];
        if (keep)
            slist[wbase + __popc(m & ((1u << lane) - 1u))] = tid;
        __syncthreads();
        int cnt = swcnt[0] + swcnt[1] + swcnt[2] + swcnt[3] +
                  swcnt[4] + swcnt[5] + swcnt[6] + swcnt[7];

        for (int g = 0; g < cnt; g++) {
            const int idx = slist[g];
            const float4 f0 = sg[4 * idx + 0];
            const float4 f1 = sg[4 * idx + 1];
            const float4 f2 = sg[4 * idx + 2];
            const float4 f3 = sg[4 * idx + 3];

            const float dy = vy - f1.w;
            const float dz = vz - f2.x;
            const float u0 = x0 - f1.z;
            const float w  = f2.y;
            const float r  = f2.w;

            // m(u) = a*u^2 + bb*u + cc   (log2 domain, <= 0)
            const float bb = fmaf(f0.w, dy, f1.x * dz);
            const float cc = fmaf(dy, fmaf(f0.y, dy, f1.y * dz), (f0.z * dz) * dz);

            const float m0 = fmaf(fmaf(f0.x, u0, bb), u0, cc);
            // G0 exponent = 2ah*u0 + ah^2 + bb*h ; clamp to avoid inf (only
            // binds where the entire run is < 2^-4000)
            const float g0 = fminf(fmaf(f3.x, u0, fmaf(bb, h, f3.y)), 100.f);

            float E = ex2_approx(m0);
            float G = ex2_approx(g0);

#pragma unroll
            for (int v = 0; v < RUNX; v++) {
                acc[v] = fmaf(E, w, acc[v]);
                if (v < RUNX - 1) { E *= G; G *= r; }
            }
        }
        __syncthreads();
    }

    const size_t vidx = ((size_t)gz * DIMY + gy) * DIMX + gx;
    *reinterpret_cast<float4*>(out + vidx)     = make_float4(acc[0], acc[1], acc[2], acc[3]);
    *reinterpret_cast<float4*>(out + vidx + 4) = make_float4(acc[4], acc[5], acc[6], acc[7]);
}

extern "C" void kernel_launch(void* const* d_in, const int* in_sizes, int n_in,
                              void* d_out, int out_size) {
    const float* positions = (const float*)d_in[0];
    const float* scales    = (const float*)d_in[1];
    const float* rotations = (const float*)d_in[2];
    const float* density   = (const float*)d_in[3];
    const int N = in_sizes[3];

    precompute_kernel<<<(N + 255) / 256, 256>>>(positions, scales, rotations, density, N);

    dim3 grid(DIMX / RUNX, DIMY / TILE_Y, DIMZ / TILE_Z);  // (16, 8, 8) = 1024
    voxelize_kernel<<<grid, 256>>>((float*)d_out, N);
}

// round 5
// speedup vs baseline: 1.4702x; 1.1121x over previous
#include <cuda_runtime.h>
#include <cuda_bf16.h>
#include <cstdint>

// ---------------------------------------------------------------------------
// Voxelizer: volume[z,y,x] = sum_n density[n] * exp(-0.5 * d^T C_n^{-1} d)
//
// R5: - 2 y-rows per thread (16 voxels) -> 4096 total warps = single wave
//     - even/odd stride-2 Gaussian recurrence (half the chain depth)
//     - G0 from m1-m0 (drops 4th param vector; 3 float4/gaussian)
//     - 128-thread blocks, 1024 blocks, __launch_bounds__(128,8)
// ---------------------------------------------------------------------------

#define MAX_N 4096
__device__ float4 g_gauss[3 * MAX_N];

#define DIMX 128
#define DIMY 128
#define DIMZ 128
#define RUNX 8
#define TILE_Y 16
#define TILE_Z 16
#define HSTEP (2.0f / 127.0f)

__device__ __forceinline__ float ex2_approx(float x) {
    float y;
    asm("ex2.approx.ftz.f32 %0, %1;" : "=f"(y) : "f"(x));
    return y;
}

__global__ void precompute_kernel(const float* __restrict__ pos,
                                  const float* __restrict__ scl,
                                  const float* __restrict__ rot,
                                  const float* __restrict__ den,
                                  int N) {
    int i = blockIdx.x * blockDim.x + threadIdx.x;
    if (i >= N) return;

    float qw = rot[4 * i + 0], qx = rot[4 * i + 1];
    float qy = rot[4 * i + 2], qz = rot[4 * i + 3];
    float qn = rsqrtf(qw * qw + qx * qx + qy * qy + qz * qz);
    qw *= qn; qx *= qn; qy *= qn; qz *= qn;

    float r00 = 1.f - 2.f * (qy * qy + qz * qz);
    float r01 = 2.f * (qx * qy - qw * qz);
    float r02 = 2.f * (qx * qz + qw * qy);
    float r10 = 2.f * (qx * qy + qw * qz);
    float r11 = 1.f - 2.f * (qx * qx + qz * qz);
    float r12 = 2.f * (qy * qz - qw * qx);
    float r20 = 2.f * (qx * qz - qw * qy);
    float r21 = 2.f * (qy * qz + qw * qx);
    float r22 = 1.f - 2.f * (qx * qx + qy * qy);

    float s0 = scl[3 * i + 0], s1 = scl[3 * i + 1], s2 = scl[3 * i + 2];
    float i0 = 1.f / (s0 * s0 + 1e-8f);
    float i1 = 1.f / (s1 * s1 + 1e-8f);
    float i2 = 1.f / (s2 * s2 + 1e-8f);

    float c00 = r00 * r00 * i0 + r01 * r01 * i1 + r02 * r02 * i2;
    float c11 = r10 * r10 * i0 + r11 * r11 * i1 + r12 * r12 * i2;
    float c22 = r20 * r20 * i0 + r21 * r21 * i1 + r22 * r22 * i2;
    float c01 = r00 * r10 * i0 + r01 * r11 * i1 + r02 * r12 * i2;
    float c02 = r00 * r20 * i0 + r01 * r21 * i1 + r02 * r22 * i2;
    float c12 = r10 * r20 * i0 + r11 * r21 * i1 + r12 * r22 * i2;

    const float k = -0.5f * 1.4426950408889634f;  // exp(-0.5m) = 2^(k*m)

    float smax2 = fmaxf(s0 * s0, fmaxf(s1 * s1, s2 * s2)) + 1e-8f;
    float rcut2 = 40.f * smax2;  // skipped term <= exp(-20) ~ 2e-9

    float p0 = pos[3 * i + 0];  // z
    float p1 = pos[3 * i + 1];  // y
    float p2 = pos[3 * i + 2];  // x (fast axis)

    float a  = k * c22;                    // coef of dx^2 (log2 domain, < 0)
    float rr = exp2f(2.f * a * HSTEP * HSTEP);  // per-step ratio of G, (0.5,1]

    // Layout (3 x float4 per gaussian):
    //  f0 = (a, k*c11 [dy^2], k*c00 [dz^2], 2k*c12 [u*dy])
    //  f1 = (2k*c02 [u*dz], 2k*c01 [dy*dz], px, py)
    //  f2 = (pz, density, rcut2, r)
    g_gauss[3 * i + 0] = make_float4(a, k * c11, k * c00, 2.f * k * c12);
    g_gauss[3 * i + 1] = make_float4(2.f * k * c02, 2.f * k * c01, p2, p1);
    g_gauss[3 * i + 2] = make_float4(p0, den[i], rcut2, rr);
}

// Tile: 8(x) x 16(y) x 16(z); 128 threads, each owns rows (ty, ty+8) x 8 x.
__global__ __launch_bounds__(128, 8)
void voxelize_kernel(float* __restrict__ out, int N) {
    __shared__ float4 sg[3 * 256];
    __shared__ int slist[256];
    __shared__ int swcnt[4];

    const float h = HSTEP;
    const int tid  = threadIdx.x;
    const int lane = tid & 31;
    const int wid  = tid >> 5;

    const int ty = tid & 7;         // y in [0,8); second row at ty+8
    const int tz = tid >> 3;        // z in [0,16)

    const int gx = blockIdx.x * RUNX;
    const int gy = blockIdx.y * TILE_Y + ty;
    const int gz = blockIdx.z * TILE_Z + tz;

    const float x0 = -1.f + h * (float)gx;
    const float vyA = -1.f + h * (float)gy;
    const float vyB = vyA + 8.f * h;
    const float vz  = -1.f + h * (float)gz;

    // Tile bounding box for culling
    const float cx = -1.f + h * ((float)(blockIdx.x * RUNX)   + (RUNX   - 1) * 0.5f);
    const float cy = -1.f + h * ((float)(blockIdx.y * TILE_Y) + (TILE_Y - 1) * 0.5f);
    const float cz = -1.f + h * ((float)(blockIdx.z * TILE_Z) + (TILE_Z - 1) * 0.5f);
    const float hx = (RUNX   - 1) * 0.5f * h;
    const float hy = (TILE_Y - 1) * 0.5f * h;
    const float hz = (TILE_Z - 1) * 0.5f * h;

    float accA[RUNX], accB[RUNX];
#pragma unroll
    for (int v = 0; v < RUNX; v++) { accA[v] = 0.f; accB[v] = 0.f; }

    for (int base = 0; base < N; base += 256) {
        const int nch = min(256, N - base);

        for (int j = tid; j < 3 * nch; j += 128)
            sg[j] = g_gauss[3 * base + j];
        __syncthreads();

        // Conservative cull over up to 256 candidates with 128 threads,
        // deterministic two-pass ballot compaction.
        int cnt = 0;
#pragma unroll
        for (int half = 0; half < 2; half++) {
            const int c = half * 128 + tid;
            bool keep = false;
            if (c < nch) {
                float px = sg[3 * c + 1].z;
                float py = sg[3 * c + 1].w;
                float pz = sg[3 * c + 2].x;
                float dx = fmaxf(fabsf(px - cx) - hx, 0.f);
                float dy = fmaxf(fabsf(py - cy) - hy, 0.f);
                float dz = fmaxf(fabsf(pz - cz) - hz, 0.f);
                float d2 = dx * dx + dy * dy + dz * dz;
                keep = (d2 <= sg[3 * c + 2].z);
            }
            unsigned m = __ballot_sync(0xffffffffu, keep);
            if (lane == 0) swcnt[wid] = __popc(m);
            __syncthreads();
            int wbase = cnt;
#pragma unroll
            for (int w = 0; w < 4; w++)
                if (w < wid) wbase += swcnt[w];
            if (keep)
                slist[wbase + __popc(m & ((1u << lane) - 1u))] = c;
            cnt += swcnt[0] + swcnt[1] + swcnt[2] + swcnt[3];
            __syncthreads();
        }

        for (int g = 0; g < cnt; g++) {
            const int idx = slist[g];
            const float4 f0 = sg[3 * idx + 0];
            const float4 f1 = sg[3 * idx + 1];
            const float4 f2 = sg[3 * idx + 2];

            // Row-independent precomputation
            const float dz  = vz - f2.x;
            const float u0  = x0 - f1.z;
            const float u1  = u0 + h;
            const float w   = f2.y;
            const float r   = f2.w;
            const float r2  = r * r;
            const float r4  = r2 * r2;
            const float bxz = f1.x * dz;          // 2k*c02 * dz  (bb part)
            const float t1  = f1.y * dz;          // 2k*c01 * dz  (cc part)
            const float t2  = (f0.z * dz) * dz;   // k*c00 * dz^2 (cc part)

#pragma unroll
            for (int row = 0; row < 2; row++) {
                const float vy = row ? vyB : vyA;
                float* acc = row ? accB : accA;

                const float dy = vy - f1.w;
                const float bb = fmaf(f0.w, dy, bxz);
                const float cc = fmaf(dy, fmaf(f0.y, dy, t1), t2);

                const float m0 = fmaf(fmaf(f0.x, u0, bb), u0, cc);
                const float m1 = fmaf(fmaf(f0.x, u1, bb), u1, cc);
                // G0 exponent; clamp only binds where entire row underflows
                const float g0 = fminf(m1 - m0, 100.f);

                const float E0 = ex2_approx(m0);
                const float G0 = ex2_approx(g0);

                // Even/odd stride-2 chains:
                //  E_{v+2} = E_v * H_v ; H_{v+2} = H_v * r^4
                //  H0 = G0^2 r ; H1 = H0 r^2
                const float E1 = E0 * G0;
                const float H0 = (G0 * G0) * r;
                const float H1 = H0 * r2;
                const float E2 = E0 * H0;
                const float E3 = E1 * H1;
                const float H2 = H0 * r4;
                const float H3 = H1 * r4;
                const float E4 = E2 * H2;
                const float E5 = E3 * H3;
                const float H4 = H2 * r4;
                const float H5 = H3 * r4;
                const float E6 = E4 * H4;
                const float E7 = E5 * H5;

                acc[0] = fmaf(E0, w, acc[0]);
                acc[1] = fmaf(E1, w, acc[1]);
                acc[2] = fmaf(E2, w, acc[2]);
                acc[3] = fmaf(E3, w, acc[3]);
                acc[4] = fmaf(E4, w, acc[4]);
                acc[5] = fmaf(E5, w, acc[5]);
                acc[6] = fmaf(E6, w, acc[6]);
                acc[7] = fmaf(E7, w, acc[7]);
            }
        }
        __syncthreads();
    }

    const size_t vA = ((size_t)gz * DIMY + gy) * DIMX + gx;
    const size_t vB = ((size_t)gz * DIMY + (gy + 8)) * DIMX + gx;
    *reinterpret_cast<float4*>(out + vA)     = make_float4(accA[0], accA[1], accA[2], accA[3]);
    *reinterpret_cast<float4*>(out + vA + 4) = make_float4(accA[4], accA[5], accA[6], accA[7]);
    *reinterpret_cast<float4*>(out + vB)     = make_float4(accB[0], accB[1], accB[2], accB[3]);
    *reinterpret_cast<float4*>(out + vB + 4) = make_float4(accB[4], accB[5], accB[6], accB[7]);
}

extern "C" void kernel_launch(void* const* d_in, const int* in_sizes, int n_in,
                              void* d_out, int out_size) {
    const float* positions = (const float*)d_in[0];
    const float* scales    = (const float*)d_in[1];
    const float* rotations = (const float*)d_in[2];
    const float* density   = (const float*)d_in[3];
    const int N = in_sizes[3];

    precompute_kernel<<<(N + 255) / 256, 256>>>(positions, scales, rotations, density, N);

    dim3 grid(DIMX / RUNX, DIMY / TILE_Y, DIMZ / TILE_Z);  // (16, 8, 8) = 1024
    voxelize_kernel<<<grid, 128>>>((float*)d_out, N);
}